// round 7
// baseline (speedup 1.0000x reference)
#include <cuda_runtime.h>
#include <cuda_bf16.h>
#include <stdint.h>

#define TN 2000
#define UN 50000
#define TF 16
#define OUTC (TF + 36)
#define NF 40                   // padded features: 0..35 emb, 36 count, 37..39 zero
#define KPAD 50176              // mult of 256
#define KT2 32                  // K per pipeline stage
#define NST_TOT (KPAD / KT2)    // 1568
#define MB 128                  // M per CTA (4 warps x m32)
#define NMB 16
#define TPAD (NMB * MB)         // 2048
#define NSPLIT 18               // grid = 288 CTAs ~ 2/SM
#define NTHR 128
#define NSTG 4
#define ASTR 36                               // A row stride (ints), conflict-free
#define ASTAGE_B (128 * ASTR * 4)             // 18432 B
#define BSTR 24                               // B row stride (words), conflict-free
#define BSTAGE_B (NF * BSTR * 4)              // 3840 B
#define SMEM_TOTAL (NSTG * (ASTAGE_B + BSTAGE_B))   // 89088 B

// ---------------- device scratch (static) ----------------
__device__ __nv_bfloat16 g_UT[(size_t)NF * KPAD];   // paired-word layout
__device__ float g_part[(size_t)NSPLIT * TPAD * NF];

__device__ __forceinline__ uint32_t smem_u32(const void* p) {
    uint32_t a;
    asm("{ .reg .u64 t; cvta.to.shared.u64 t, %1; cvt.u32.u64 %0, t; }" : "=r"(a) : "l"(p));
    return a;
}
__device__ __forceinline__ void mma16816(float* c, uint32_t a0, uint32_t a1,
                                         uint32_t a2, uint32_t a3,
                                         uint32_t b0, uint32_t b1) {
    asm volatile("mma.sync.aligned.m16n8k16.row.col.f32.bf16.bf16.f32 "
                 "{%0,%1,%2,%3}, {%4,%5,%6,%7}, {%8,%9}, {%0,%1,%2,%3};"
                 : "+f"(c[0]), "+f"(c[1]), "+f"(c[2]), "+f"(c[3])
                 : "r"(a0), "r"(a1), "r"(a2), "r"(a3), "r"(b0), "r"(b1));
}
__device__ __forceinline__ uint32_t pk(int2 m) {
    return (uint32_t)(m.x + (m.y << 16)) * 0x3F80u;
}

// ---------------- prep: 256 users/block, paired-word transposed output ----------------
__global__ void __launch_bounds__(256) prep_kernel(
        const unsigned int* __restrict__ us,
        const float* __restrict__ e0, const float* __restrict__ e1,
        const float* __restrict__ e2, const float* __restrict__ e3,
        const float* __restrict__ e4, const float* __restrict__ e5) {
    __shared__ float sT[NF * 256];
    __shared__ int s_is64;
    const int tid = threadIdx.x;
    const int u0 = blockIdx.x * 256;

    if (tid == 0) {
        unsigned probe = 0;
#pragma unroll
        for (int w = 1; w < 32; w += 2) probe |= us[w];
        s_is64 = (probe == 0u);   // int64 serialization -> zero high words
    }
    __syncthreads();
    const bool is64 = (s_is64 != 0);

    const int u = u0 + tid;
    if (u < UN) {
        const float* tabs[6] = {e0, e1, e2, e3, e4, e5};
#pragma unroll
        for (int i = 0; i < 6; i++) {
            int elem = u * 6 + i;
            unsigned idx = us[is64 ? (2 * elem) : elem];
            const float* row = tabs[i] + (size_t)idx * 6;
#pragma unroll
            for (int j = 0; j < 6; j++) sT[(i * 6 + j) * 256 + tid] = row[j];
        }
        sT[36 * 256 + tid] = 1.0f;   // count column
        sT[37 * 256 + tid] = 0.0f;
        sT[38 * 256 + tid] = 0.0f;
        sT[39 * 256 + tid] = 0.0f;
    } else {
#pragma unroll
        for (int f = 0; f < NF; f++) sT[f * 256 + tid] = 0.0f;
    }
    __syncthreads();

    // write transposed, paired-word permutation within each 64-element block:
    // orig word p -> w' = (p>>3)*8 + (p&3)*2 + ((p>>2)&1)
#pragma unroll
    for (int i = 0; i < NF * 128 / 256; i++) {
        int idx = tid + i * 256;
        int f = idx >> 7, p = idx & 127;
        int blk = p >> 5, pw = p & 31;
        int wp = ((pw >> 3) << 3) + ((pw & 3) << 1) + ((pw >> 2) & 1);
        __nv_bfloat162 v = __floats2bfloat162_rn(sT[f * 256 + 2 * p],
                                                 sT[f * 256 + 2 * p + 1]);
        *(__nv_bfloat162*)(&g_UT[(size_t)f * KPAD + u0 + blk * 64 + wp * 2]) = v;
    }
}

// ---------------- accum: cp.async depth-4 HMMA GEMM, m32/warp ----------------
__device__ __forceinline__ void issue_stage(uint32_t smb, int s, int k0,
                                            const int* __restrict__ tum,
                                            int t0, int tid) {
    uint32_t aB = smb + s * ASTAGE_B;
    uint32_t bB = smb + NSTG * ASTAGE_B + s * BSTAGE_B;
    // A: 128 rows x 32 ints = 1024 16B chunks, 8 per thread
#pragma unroll
    for (int i = 0; i < 8; i++) {
        int q = tid + i * NTHR;
        int r = q >> 3;
        int ci = q & 7;
        uint32_t dst = aB + (uint32_t)r * (ASTR * 4) + (uint32_t)ci * 16u;
        const int* src = tum + (size_t)(t0 + r) * UN + (k0 + ci * 4);
        uint32_t sz = ((t0 + r) < TN && (k0 + ci * 4) < UN) ? 16u : 0u;
        asm volatile("cp.async.cg.shared.global [%0], [%1], 16, %2;"
                     :: "r"(dst), "l"(src), "r"(sz));
    }
    // B: 40 rows x 16 words = 160 16B chunks
#pragma unroll
    for (int i = 0; i < 2; i++) {
        int q = tid + i * NTHR;
        if (q < NF * 4) {
            int r = q >> 2;
            uint32_t dst = bB + (uint32_t)r * (BSTR * 4) + (uint32_t)(q & 3) * 16u;
            const __nv_bfloat16* src = g_UT + (size_t)r * KPAD + k0 + (q & 3) * 8;
            asm volatile("cp.async.cg.shared.global [%0], [%1], 16, 16;"
                         :: "r"(dst), "l"(src));
        }
    }
}

__device__ __forceinline__ void compute_stage(const char* sm, int s, float acc[2][5][4],
                                              int w, int g, int cc) {
    const int* aP = (const int*)(sm + s * ASTAGE_B);
    const uint32_t* bP = (const uint32_t*)(sm + NSTG * ASTAGE_B + s * BSTAGE_B);
    const int rowA = (32 * w + g) * ASTR + 2 * cc;
#pragma unroll
    for (int ks = 0; ks < 2; ks++) {
        uint32_t bf[10];
        const uint32_t* bb = bP + g * BSTR + ks * 8 + cc * 2;
#pragma unroll
        for (int nb = 0; nb < 5; nb++) {
            uint2 v = *(const uint2*)(bb + nb * 8 * BSTR);
            bf[2 * nb] = v.x;
            bf[2 * nb + 1] = v.y;
        }
#pragma unroll
        for (int mh = 0; mh < 2; mh++) {
            const int* p0 = aP + rowA + mh * 16 * ASTR + 16 * ks;
            int2 x0 = *(const int2*)(p0);
            int2 x2 = *(const int2*)(p0 + 8);
            int2 x1 = *(const int2*)(p0 + 8 * ASTR);
            int2 x3 = *(const int2*)(p0 + 8 * ASTR + 8);
            uint32_t a0 = pk(x0), a1 = pk(x1), a2 = pk(x2), a3 = pk(x3);
#pragma unroll
            for (int nb = 0; nb < 5; nb++)
                mma16816(acc[mh][nb], a0, a1, a2, a3, bf[2 * nb], bf[2 * nb + 1]);
        }
    }
}

__global__ void __launch_bounds__(NTHR, 2) accum_kernel(const int* __restrict__ tum) {
    extern __shared__ char sm[];
    const int tid = threadIdx.x;
    const int w = tid >> 5, lane = tid & 31;
    const int g = lane >> 2, cc = lane & 3;
    const int mb = blockIdx.x & (NMB - 1);
    const int sp = blockIdx.x >> 4;
    const int t0 = mb * MB;
    const uint32_t smb = smem_u32(sm);

    const int J = (NST_TOT - sp + NSPLIT - 1) / NSPLIT;

    float acc[2][5][4];
#pragma unroll
    for (int mh = 0; mh < 2; mh++)
#pragma unroll
        for (int nb = 0; nb < 5; nb++)
#pragma unroll
            for (int q = 0; q < 4; q++) acc[mh][nb][q] = 0.0f;

    // prologue: NSTG-1 stages in flight
#pragma unroll
    for (int s = 0; s < NSTG - 1; s++) {
        issue_stage(smb, s, (sp + s * NSPLIT) * KT2, tum, t0, tid);
        asm volatile("cp.async.commit_group;");
    }
    for (int j = 0; j < J; j++) {
        asm volatile("cp.async.wait_group %0;" :: "n"(NSTG - 2));
        __syncthreads();   // group j data visible to all; compute(j-1) done by all
        int nj = j + NSTG - 1;
        if (nj < J)
            issue_stage(smb, nj & (NSTG - 1), (sp + nj * NSPLIT) * KT2, tum, t0, tid);
        asm volatile("cp.async.commit_group;");
        compute_stage(sm, j & (NSTG - 1), acc, w, g, cc);
    }

    // epilogue: write partials [sp][t][40]
    float* part = g_part + (size_t)sp * TPAD * NF;
#pragma unroll
    for (int mh = 0; mh < 2; mh++) {
        int tA = t0 + 32 * w + 16 * mh + g;
#pragma unroll
        for (int nb = 0; nb < 5; nb++) {
            int col = nb * 8 + 2 * cc;
            if (tA < TN)
                *(float2*)(&part[(size_t)tA * NF + col]) =
                    make_float2(acc[mh][nb][0], acc[mh][nb][1]);
            if (tA + 8 < TN)
                *(float2*)(&part[(size_t)(tA + 8) * NF + col]) =
                    make_float2(acc[mh][nb][2], acc[mh][nb][3]);
        }
    }
}

// ---------------- finalize ----------------
__global__ void finalize_kernel(const float* __restrict__ T_static,
                                float* __restrict__ out) {
    int i = blockIdx.x * blockDim.x + threadIdx.x;
    if (i >= TN * OUTC) return;
    int t = i / OUTC;
    int c = i - t * OUTC;
    if (c < TF) {
        out[i] = T_static[t * TF + c];
    } else {
        int f = c - TF;
        float s = 0.0f, cnt = 0.0f;
        const float* base = g_part + (size_t)t * NF;
#pragma unroll
        for (int k = 0; k < NSPLIT; k++) {
            const float* q = base + (size_t)k * (TPAD * NF);
            s += q[f];
            cnt += q[36];
        }
        out[i] = s / cnt;
    }
}

extern "C" void kernel_launch(void* const* d_in, const int* in_sizes, int n_in,
                              void* d_out, int out_size) {
    const float* T_static = (const float*)d_in[0];
    const unsigned int* us = (const unsigned int*)d_in[1];
    const int* tum = (const int*)d_in[2];
    const float* e0 = (const float*)d_in[3];
    const float* e1 = (const float*)d_in[4];
    const float* e2 = (const float*)d_in[5];
    const float* e3 = (const float*)d_in[6];
    const float* e4 = (const float*)d_in[7];
    const float* e5 = (const float*)d_in[8];
    float* out = (float*)d_out;

    cudaFuncSetAttribute(accum_kernel, cudaFuncAttributeMaxDynamicSharedMemorySize,
                         SMEM_TOTAL);
    prep_kernel<<<KPAD / 256, 256>>>(us, e0, e1, e2, e3, e4, e5);
    accum_kernel<<<NMB * NSPLIT, NTHR, SMEM_TOTAL>>>(tum);
    finalize_kernel<<<(TN * OUTC + 255) / 256, 256>>>(T_static, out);
}

// round 8
// speedup vs baseline: 1.0924x; 1.0924x over previous
#include <cuda_runtime.h>
#include <cuda_bf16.h>
#include <stdint.h>

#define TN 2000
#define UN 50000
#define TF 16
#define OUTC (TF + 36)
#define NF 40                   // padded features: 0..35 emb, 36 count, 37..39 zero
#define KPAD 50176              // mult of 64
#define KT2 64                  // K per pipeline stage
#define NST_TOT (KPAD / KT2)    // 784
#define MB 128                  // M per CTA (4 warps x m32)
#define NMB 16
#define TPAD (NMB * MB)         // 2048
#define NSPLIT 18               // grid = 288 CTAs ~ 2/SM
#define NTHR 128
#define ASTR 72                              // A row stride (ints): conflict-free
#define ASTAGE_B (128 * ASTR * 4)            // 36864 B
#define BSTR 40                              // B row stride (words): conflict-free
#define BSTAGE_B (NF * BSTR * 4)             // 6400 B
#define SMEM_TOTAL (2 * (ASTAGE_B + BSTAGE_B))   // 86528 B

// ---------------- device scratch (static) ----------------
__device__ __nv_bfloat16 g_UT[(size_t)NF * KPAD];   // paired-word layout per 64k block
__device__ float g_part[(size_t)NSPLIT * TPAD * NF];

__device__ __forceinline__ uint32_t smem_u32(const void* p) {
    uint32_t a;
    asm("{ .reg .u64 t; cvta.to.shared.u64 t, %1; cvt.u32.u64 %0, t; }" : "=r"(a) : "l"(p));
    return a;
}
__device__ __forceinline__ void mma16816(float* c, uint32_t a0, uint32_t a1,
                                         uint32_t a2, uint32_t a3,
                                         uint32_t b0, uint32_t b1) {
    asm volatile("mma.sync.aligned.m16n8k16.row.col.f32.bf16.bf16.f32 "
                 "{%0,%1,%2,%3}, {%4,%5,%6,%7}, {%8,%9}, {%0,%1,%2,%3};"
                 : "+f"(c[0]), "+f"(c[1]), "+f"(c[2]), "+f"(c[3])
                 : "r"(a0), "r"(a1), "r"(a2), "r"(a3), "r"(b0), "r"(b1));
}
__device__ __forceinline__ uint32_t pk(int2 m) {
    return (uint32_t)(m.x + (m.y << 16)) * 0x3F80u;
}

// ---------------- prep: direct scatter, 1 thread = 1 output bf16x2 ----------------
// Output word w' within each 64-element k-block is the paired-word permutation of
// source word p: w' = 8a + 2c + d where p = 8a + 4d + c. Inverse: a=w'>>3,
// c=(w'&7)>>1, d=w'&1.
__global__ void __launch_bounds__(256) prep_kernel(
        const unsigned int* __restrict__ us,
        const float* __restrict__ e0, const float* __restrict__ e1,
        const float* __restrict__ e2, const float* __restrict__ e3,
        const float* __restrict__ e4, const float* __restrict__ e5) {
    __shared__ int s_is64;
    if (threadIdx.x == 0) {
        unsigned probe = 0;
#pragma unroll
        for (int w = 1; w < 32; w += 2) probe |= us[w];
        s_is64 = (probe == 0u);   // int64 serialization -> zero high words
    }
    __syncthreads();
    const int is64 = s_is64;

    const int f = blockIdx.y;
    const int widx = blockIdx.x * 256 + threadIdx.x;   // word index in row f
    if (widx >= KPAD / 2) return;
    const int blk = widx >> 5, wp = widx & 31;
    const int p = ((wp >> 3) << 3) + ((wp & 1) << 2) + ((wp & 7) >> 1);
    const int u = blk * 64 + 2 * p;

    float v0 = 0.0f, v1 = 0.0f;
    if (f == 36) {
        v0 = (u < UN) ? 1.0f : 0.0f;
        v1 = (u + 1 < UN) ? 1.0f : 0.0f;
    } else if (f < 36) {
        const int i = f / 6, j = f - 6 * i;   // block-uniform
        const float* tab = (i == 0) ? e0 : (i == 1) ? e1 : (i == 2) ? e2
                         : (i == 3) ? e3 : (i == 4) ? e4 : e5;
        if (u < UN) {
            unsigned ix = us[(unsigned)(u * 6 + i) << is64];
            v0 = tab[(size_t)ix * 6 + j];
        }
        if (u + 1 < UN) {
            unsigned ix = us[(unsigned)((u + 1) * 6 + i) << is64];
            v1 = tab[(size_t)ix * 6 + j];
        }
    }
    __nv_bfloat162 v = __floats2bfloat162_rn(v0, v1);
    *(__nv_bfloat162*)(&g_UT[(size_t)f * KPAD + blk * 64 + 2 * wp]) = v;
}

// ---------------- accum: cp.async depth-2 HMMA GEMM, m32/warp (R6) ----------------
__device__ __forceinline__ void issue_stage(uint32_t smb, int s, int k0,
                                            const int* __restrict__ tum,
                                            int t0, int tid) {
    uint32_t aB = smb + s * ASTAGE_B;
    uint32_t bB = smb + 2 * ASTAGE_B + s * BSTAGE_B;
#pragma unroll
    for (int i = 0; i < 16; i++) {
        int q = tid + i * NTHR;
        int r = q >> 4;
        int c = (q & 15) << 2;
        uint32_t dst = aB + (uint32_t)r * (ASTR * 4) + (uint32_t)(q & 15) * 16u;
        const int* src = tum + (size_t)(t0 + r) * UN + (k0 + c);
        uint32_t sz = ((t0 + r) < TN && (k0 + c) < UN) ? 16u : 0u;
        asm volatile("cp.async.cg.shared.global [%0], [%1], 16, %2;"
                     :: "r"(dst), "l"(src), "r"(sz));
    }
#pragma unroll
    for (int i = 0; i < 3; i++) {
        int q = tid + i * NTHR;
        if (q < NF * 8) {
            int r = q >> 3;
            uint32_t dst = bB + (uint32_t)r * (BSTR * 4) + (uint32_t)(q & 7) * 16u;
            const __nv_bfloat16* src = g_UT + (size_t)r * KPAD + k0 + (q & 7) * 8;
            asm volatile("cp.async.cg.shared.global [%0], [%1], 16, 16;"
                         :: "r"(dst), "l"(src));
        }
    }
}

__device__ __forceinline__ void compute_stage(const char* sm, int s, float acc[2][5][4],
                                              int w, int g, int cc) {
    const int* aP = (const int*)(sm + s * ASTAGE_B);
    const uint32_t* bP = (const uint32_t*)(sm + 2 * ASTAGE_B + s * BSTAGE_B);
    const int rowA = (32 * w + g) * ASTR + 2 * cc;
#pragma unroll
    for (int ks = 0; ks < 4; ks++) {
        uint32_t bf[10];
        const uint32_t* bb = bP + g * BSTR + ks * 8 + cc * 2;
#pragma unroll
        for (int nb = 0; nb < 5; nb++) {
            uint2 v = *(const uint2*)(bb + nb * 8 * BSTR);
            bf[2 * nb] = v.x;
            bf[2 * nb + 1] = v.y;
        }
#pragma unroll
        for (int mh = 0; mh < 2; mh++) {
            const int* p0 = aP + rowA + mh * 16 * ASTR + 16 * ks;
            int2 x0 = *(const int2*)(p0);
            int2 x2 = *(const int2*)(p0 + 8);
            int2 x1 = *(const int2*)(p0 + 8 * ASTR);
            int2 x3 = *(const int2*)(p0 + 8 * ASTR + 8);
            uint32_t a0 = pk(x0), a1 = pk(x1), a2 = pk(x2), a3 = pk(x3);
#pragma unroll
            for (int nb = 0; nb < 5; nb++)
                mma16816(acc[mh][nb], a0, a1, a2, a3, bf[2 * nb], bf[2 * nb + 1]);
        }
    }
}

__global__ void __launch_bounds__(NTHR, 2) accum_kernel(const int* __restrict__ tum) {
    extern __shared__ char sm[];
    const int tid = threadIdx.x;
    const int w = tid >> 5, lane = tid & 31;
    const int g = lane >> 2, cc = lane & 3;
    const int mb = blockIdx.x & (NMB - 1);
    const int sp = blockIdx.x >> 4;
    const int t0 = mb * MB;
    const uint32_t smb = smem_u32(sm);

    const int J = (NST_TOT - sp + NSPLIT - 1) / NSPLIT;

    float acc[2][5][4];
#pragma unroll
    for (int mh = 0; mh < 2; mh++)
#pragma unroll
        for (int nb = 0; nb < 5; nb++)
#pragma unroll
            for (int q = 0; q < 4; q++) acc[mh][nb][q] = 0.0f;

    issue_stage(smb, 0, sp * KT2, tum, t0, tid);
    asm volatile("cp.async.commit_group;");

    for (int j = 0; j < J; j++) {
        __syncthreads();   // buffer (j+1)&1 free: compute(j-1) done by all warps
        if (j + 1 < J) {
            issue_stage(smb, (j + 1) & 1, (sp + (j + 1) * NSPLIT) * KT2, tum, t0, tid);
            asm volatile("cp.async.commit_group;");
            asm volatile("cp.async.wait_group 1;");   // in-order: group j retired
        } else {
            asm volatile("cp.async.wait_group 0;");
        }
        __syncthreads();
        compute_stage(sm, j & 1, acc, w, g, cc);
    }

    float* part = g_part + (size_t)sp * TPAD * NF;
#pragma unroll
    for (int mh = 0; mh < 2; mh++) {
        int tA = t0 + 32 * w + 16 * mh + g;
#pragma unroll
        for (int nb = 0; nb < 5; nb++) {
            int col = nb * 8 + 2 * cc;
            if (tA < TN)
                *(float2*)(&part[(size_t)tA * NF + col]) =
                    make_float2(acc[mh][nb][0], acc[mh][nb][1]);
            if (tA + 8 < TN)
                *(float2*)(&part[(size_t)(tA + 8) * NF + col]) =
                    make_float2(acc[mh][nb][2], acc[mh][nb][3]);
        }
    }
}

// ---------------- finalize ----------------
__global__ void finalize_kernel(const float* __restrict__ T_static,
                                float* __restrict__ out) {
    int i = blockIdx.x * blockDim.x + threadIdx.x;
    if (i >= TN * OUTC) return;
    int t = i / OUTC;
    int c = i - t * OUTC;
    if (c < TF) {
        out[i] = T_static[t * TF + c];
    } else {
        int f = c - TF;
        float s = 0.0f, cnt = 0.0f;
        const float* base = g_part + (size_t)t * NF;
#pragma unroll
        for (int k = 0; k < NSPLIT; k++) {
            const float* q = base + (size_t)k * (TPAD * NF);
            s += q[f];
            cnt += q[36];
        }
        out[i] = s / cnt;
    }
}

extern "C" void kernel_launch(void* const* d_in, const int* in_sizes, int n_in,
                              void* d_out, int out_size) {
    const float* T_static = (const float*)d_in[0];
    const unsigned int* us = (const unsigned int*)d_in[1];
    const int* tum = (const int*)d_in[2];
    const float* e0 = (const float*)d_in[3];
    const float* e1 = (const float*)d_in[4];
    const float* e2 = (const float*)d_in[5];
    const float* e3 = (const float*)d_in[6];
    const float* e4 = (const float*)d_in[7];
    const float* e5 = (const float*)d_in[8];
    float* out = (float*)d_out;

    cudaFuncSetAttribute(accum_kernel, cudaFuncAttributeMaxDynamicSharedMemorySize,
                         SMEM_TOTAL);
    dim3 pgrid((KPAD / 2 + 255) / 256, NF);
    prep_kernel<<<pgrid, 256>>>(us, e0, e1, e2, e3, e4, e5);
    accum_kernel<<<NMB * NSPLIT, NTHR, SMEM_TOTAL>>>(tum);
    finalize_kernel<<<(TN * OUTC + 255) / 256, 256>>>(T_static, out);
}